// round 13
// baseline (speedup 1.0000x reference)
#include <cuda_runtime.h>
#include <cuda_bf16.h>
#include <cstdint>

// Problem constants (dataset-fixed)
#define HDIM   256
#define KOCC   8
#define KSUBJ  16
#define NBIN   128
#define CAP    2048
#define MT     128          // rows per CTA tile (8 warps x 16 rows)
#define NYT    (CAP / MT)   // 16
#define NCOL   40           // logit cols = 5 mma n8-tiles exactly
#define NCTA_MAIN (NBIN * NYT)   // 2048

// Per-warp cp.async ring: 4 slots x 32 lanes x 8 words (two float4 granules).
#define RINGW  1024                      // words per warp ring
#define RING_TOT (8 * RINGW)             // 8192 words
// B panel: per col 264 words: [0..127] hi kpairs, [128..255] lo kpairs, pad 8.
// 264 mod 32 == 8 -> LDS.64 conflict-free (16-lane phase covers all banks).
#define SBC    264
#define B_OFF  RING_TOT                  // 8192
#define DSM_WORDS (B_OFF + NCOL * SBC)   // 18752 words = 75008 B

__device__ int g_cursor2[2][NBIN];       // parity double-buffered (zero-init)
__device__ int g_sorted[NBIN * CAP];
__device__ int g_epoch;
__device__ int g_done;

// ---------------------------------------------------------------------------
__global__ __launch_bounds__(256) void k_scatter(const int* __restrict__ xp,
                                                 const int* __restrict__ xo, int n) {
    __shared__ int hcnt[NBIN];
    __shared__ int hbase[NBIN];
    int p = (*(volatile int*)&g_epoch) & 1;
    int t = threadIdx.x;
    if (t < NBIN) hcnt[t] = 0;
    __syncthreads();
    int base = blockIdx.x * 1024;
    int occ[4], pos[4];
#pragma unroll
    for (int j = 0; j < 4; j++) {
        int i = base + j * 256 + t;
        if (i < n) { occ[j] = xp[i] * KOCC + xo[i]; pos[j] = atomicAdd(&hcnt[occ[j]], 1); }
        else occ[j] = -1;
    }
    __syncthreads();
    if (t < NBIN && hcnt[t] > 0) hbase[t] = atomicAdd(&g_cursor2[p][t], hcnt[t]);
    __syncthreads();
#pragma unroll
    for (int j = 0; j < 4; j++)
        if (occ[j] >= 0) {
            int q = hbase[occ[j]] + pos[j];
            if (q < CAP) g_sorted[occ[j] * CAP + q] = base + j * 256 + t;
        }
}

// ---------------------------------------------------------------------------
__device__ __forceinline__ uint32_t smem_u32(const void* p) {
    uint32_t a;
    asm("{ .reg .u64 t; cvta.to.shared.u64 t, %1; cvt.u32.u64 %0, t; }" : "=r"(a) : "l"(p));
    return a;
}
__device__ __forceinline__ void cpasync16(uint32_t dst, const void* src) {
    asm volatile("cp.async.cg.shared.global [%0], [%1], 16;" :: "r"(dst), "l"(src));
}
#define CP_COMMIT() asm volatile("cp.async.commit_group;" ::: "memory")
#define CP_WAIT(N)  asm volatile("cp.async.wait_group %0;" :: "n"(N) : "memory")

// fp32 pair -> bf16x2 (hi) + bf16x2 (lo residual).
__device__ __forceinline__ void split2(float a, float b, uint32_t& hi, uint32_t& lo) {
    asm("cvt.rn.bf16x2.f32 %0, %1, %2;" : "=r"(hi) : "f"(b), "f"(a));
    float ha = __uint_as_float(hi << 16);
    float hb = __uint_as_float(hi & 0xffff0000u);
    float ra = a - ha, rb = b - hb;
    asm("cvt.rn.bf16x2.f32 %0, %1, %2;" : "=r"(lo) : "f"(rb), "f"(ra));
}

__device__ __forceinline__ void mma16816(float& d0, float& d1, float& d2, float& d3,
                                         uint32_t a0, uint32_t a1, uint32_t a2, uint32_t a3,
                                         uint32_t b0, uint32_t b1) {
    asm volatile(
        "mma.sync.aligned.m16n8k16.row.col.f32.bf16.bf16.f32 "
        "{%0,%1,%2,%3}, {%4,%5,%6,%7}, {%8,%9}, {%0,%1,%2,%3};"
        : "+f"(d0), "+f"(d1), "+f"(d2), "+f"(d3)
        : "r"(a0), "r"(a1), "r"(a2), "r"(a3), "r"(b0), "r"(b1));
}

__device__ __forceinline__ void cta_done() {
    int v = atomicAdd(&g_done, 1);
    if ((v & (NCTA_MAIN - 1)) == NCTA_MAIN - 1) atomicAdd(&g_epoch, 1);
}

// ---------------------------------------------------------------------------
// Permuted-k mapping (A and B identical, D unchanged):
//   slot "kpair tig"   <- actual kpair 2*tig  (within each k16 chunk)
//   slot "kpair tig+4" <- actual kpair 2*tig+1
// A path: lane cp.asyncs its OWN two 16B granules per chunk into a per-lane
// smem ring; consumption is per-thread (wait_group + LDS.128). No barriers.
__global__ __launch_bounds__(256, 3) void k_main(
    const float* __restrict__ X,
    const float* __restrict__ Wp, const float* __restrict__ bp,
    const float* __restrict__ Wo, const float* __restrict__ bo,
    const float* __restrict__ Ws, const float* __restrict__ bs2,
    const int* __restrict__ subj, float* __restrict__ out, int n)
{
    __shared__ int   rowidx[MT];
    __shared__ float biasz[NCOL];
    extern __shared__ uint32_t sm[];

    int p = (*(volatile int*)&g_epoch) & 1;
    int bin  = blockIdx.x;
    int t = threadIdx.x;

    if (bin == 0 && blockIdx.y == 0 && t < NBIN) g_cursor2[1 - p][t] = 0;

    int cnt  = g_cursor2[p][bin];
    int base = blockIdx.y * MT;
    if (base >= cnt) { if (t == 0) cta_done(); return; }
    int nrows = min(MT, cnt - base);
    int phase = bin >> 3, occl = bin & 7;
    int lane = t & 31, w = t >> 5;
    int g = lane >> 2, tig = lane & 3;

    if (t < MT)
        rowidx[t] = g_sorted[bin * CAP + base + ((t < nrows) ? t : 0)];
    if (t < NCOL)
        biasz[t] = (t < 16) ? bp[t]
                 : (t < 24) ? bo[phase * KOCC + (t - 16)]
                            : bs2[bin * KSUBJ + (t - 24)];
    __syncthreads();          // rowidx ready

    const int r0 = w * 16;
    const int pp = (lane >> 2) & 1;       // ring swizzle selector
    const int ringw = w * RINGW + lane * 8;
    const uint32_t smb = smem_u32(sm);

    // lane-private gmem sources (its own fragment granules)
    const float* xv0 = X + (size_t)rowidx[r0 + g] * HDIM + tig * 4;
    const float* xv1 = X + (size_t)rowidx[r0 + g + 8] * HDIM + tig * 4;

    auto issue = [&](int s) {
        uint32_t dst = smb + (ringw + (s & 3) * 256) * 4;
        cpasync16(dst + pp * 16,       xv0 + s * 16);
        cpasync16(dst + (1 - pp) * 16, xv1 + s * 16);
        CP_COMMIT();
    };

    issue(0); issue(1); issue(2);

    // ---- stage B panel (40 x 256) bf16 hi/lo interleaved ------------------
    auto wrow = [&](int col) -> const float* {
        if (col < 16)      return Wp + col * HDIM;
        else if (col < 24) return Wo + (phase * KOCC + col - 16) * HDIM;
        else               return Ws + (bin * KSUBJ + col - 24) * HDIM;
    };
#pragma unroll
    for (int j = 0; j < 10; j++) {
        int u   = t + j * 256;
        int col = u >> 6, f = u & 63;
        float4 wv = ((const float4*)wrow(col))[f];
        uint32_t h0, l0, h1, l1;
        split2(wv.x, wv.y, h0, l0);
        split2(wv.z, wv.w, h1, l1);
        *(uint2*)&sm[B_OFF + col * SBC + 2 * f]       = make_uint2(h0, h1);
        *(uint2*)&sm[B_OFF + col * SBC + 128 + 2 * f] = make_uint2(l0, l1);
    }
    __syncthreads();          // B ready (warps then run decoupled)

    float acc[5][4];
#pragma unroll
    for (int nt = 0; nt < 5; nt++)
#pragma unroll
        for (int i = 0; i < 4; i++) acc[nt][i] = 0.f;

#pragma unroll
    for (int c = 0; c < 16; c++) {        // chunk = k16 = one mma k-step
        if (c <= 12) issue(c + 3);
        if (c <= 12)      CP_WAIT(3);
        else if (c == 13) CP_WAIT(2);
        else if (c == 14) CP_WAIT(1);
        else              CP_WAIT(0);

        const float4* vr = (const float4*)(sm + ringw + (c & 3) * 256);
        float4 v0 = vr[pp];               // row r0+g   fragment (kpairs 2tig,2tig+1)
        float4 v1 = vr[1 - pp];           // row r0+g+8 fragment
        uint32_t a0h, a0l, a1h, a1l, a2h, a2l, a3h, a3l;
        split2(v0.x, v0.y, a0h, a0l);
        split2(v0.z, v0.w, a2h, a2l);
        split2(v1.x, v1.y, a1h, a1l);
        split2(v1.z, v1.w, a3h, a3l);
        int kb = c * 8 + 2 * tig;
#pragma unroll
        for (int nt = 0; nt < 5; nt++) {
            int colw = B_OFF + (nt * 8 + g) * SBC + kb;
            uint2 bh = *(const uint2*)&sm[colw];         // hi kpairs 2tig,2tig+1
            uint2 bl = *(const uint2*)&sm[colw + 128];   // lo
            mma16816(acc[nt][0], acc[nt][1], acc[nt][2], acc[nt][3],
                     a0h, a1h, a2h, a3h, bh.x, bh.y);
            mma16816(acc[nt][0], acc[nt][1], acc[nt][2], acc[nt][3],
                     a0h, a1h, a2h, a3h, bl.x, bl.y);
            mma16816(acc[nt][0], acc[nt][1], acc[nt][2], acc[nt][3],
                     a0l, a1l, a2l, a3l, bh.x, bh.y);
        }
    }

    // ---- epilogue: D -> smem logits [128][41] (aliases rings), softmax ----
    __syncthreads();          // all warps done with rings
    float* lg = (float*)sm;               // 5248 words <= 8192 (ring area)
#pragma unroll
    for (int nt = 0; nt < 5; nt++) {
        int col = nt * 8 + 2 * tig;
        lg[(r0 + g) * 41 + col]         = acc[nt][0];
        lg[(r0 + g) * 41 + col + 1]     = acc[nt][1];
        lg[(r0 + g + 8) * 41 + col]     = acc[nt][2];
        lg[(r0 + g + 8) * 41 + col + 1] = acc[nt][3];
    }
    __syncthreads();

    if (t < nrows) {
        const float* Lr = lg + t * 41;
        int orig = rowidx[t];
        float L[NCOL];
#pragma unroll
        for (int j = 0; j < NCOL; j++) L[j] = Lr[j] + biasz[j];

        float m1 = L[0];
#pragma unroll
        for (int j = 1; j < 16; j++) m1 = fmaxf(m1, L[j]);
        float s1 = 0.f;
#pragma unroll
        for (int j = 0; j < 16; j++) s1 += expf(L[j] - m1);
        float p1 = expf(L[phase] - m1) / s1;

        float m2 = L[16];
#pragma unroll
        for (int j = 17; j < 24; j++) m2 = fmaxf(m2, L[j]);
        float s2 = 0.f;
#pragma unroll
        for (int j = 16; j < 24; j++) s2 += expf(L[j] - m2);
        float p2 = expf(L[16 + occl] - m2) / s2;

        int sj = subj[orig];
        float m3 = L[24];
#pragma unroll
        for (int j = 25; j < 40; j++) m3 = fmaxf(m3, L[j]);
        float s3 = 0.f;
#pragma unroll
        for (int j = 24; j < 40; j++) s3 += expf(L[j] - m3);
        float p3 = expf(L[24 + sj] - m3) / s3;

        float po = p1 * p2;
        out[orig]         = p1;
        out[n + orig]     = po;
        out[2 * n + orig] = po * p3;
    }

    __syncthreads();
    if (t == 0) cta_done();
}

// ---------------------------------------------------------------------------
extern "C" void kernel_launch(void* const* d_in, const int* in_sizes, int n_in,
                              void* d_out, int out_size) {
    const float* X  = (const float*)d_in[0];
    const float* Wp = (const float*)d_in[1];
    const float* bp = (const float*)d_in[2];
    const float* Wo = (const float*)d_in[3];
    const float* bo = (const float*)d_in[4];
    const float* Ws = (const float*)d_in[5];
    const float* bs = (const float*)d_in[6];
    const int*   xp = (const int*)d_in[7];
    const int*   xo = (const int*)d_in[8];
    const int*   xs = (const int*)d_in[9];
    int n = in_sizes[0] / HDIM;
    float* out = (float*)d_out;

    static int cfg = 0;
    if (!cfg) {
        cudaFuncSetAttribute(k_main, cudaFuncAttributeMaxDynamicSharedMemorySize,
                             DSM_WORDS * 4);
        cfg = 1;
    }

    k_scatter<<<(n + 1023) / 1024, 256>>>(xp, xo, n);
    dim3 grid(NBIN, NYT);
    k_main<<<grid, 256, DSM_WORDS * 4>>>(X, Wp, bp, Wo, bo, Ws, bs, xs, out, n);
}

// round 17
// speedup vs baseline: 1.4241x; 1.4241x over previous
#include <cuda_runtime.h>
#include <cuda_bf16.h>
#include <cstdint>

// Problem constants (dataset-fixed)
#define HDIM   256
#define KOCC   8
#define KSUBJ  16
#define NBIN   128
#define CAP    2048
#define MT     128          // rows per CTA tile (8 warps x 16 rows)
#define NYT    (CAP / MT)   // 16
#define NCOL   40           // logit cols = 5 mma n8-tiles exactly
#define NCTA_MAIN (NBIN * NYT)   // 2048

// B panel: per col, 128 kpairs (uint32 bf16x2), col stride 136 words.
// half-warp LDS.64 phase covers all 32 banks -> conflict-free.
#define SBW    136
#define B_HI   0
#define B_LO   (NCOL * SBW)              // 5440
#define DSM_WORDS (2 * NCOL * SBW)       // 10880 words = 43.52 KB

__device__ int g_cursor2[2][NBIN];       // parity double-buffered (zero-init)
__device__ int g_sorted[NBIN * CAP];
__device__ int g_epoch;
__device__ int g_done;

// ---------------------------------------------------------------------------
__global__ __launch_bounds__(256) void k_scatter(const int* __restrict__ xp,
                                                 const int* __restrict__ xo, int n) {
    __shared__ int hcnt[NBIN];
    __shared__ int hbase[NBIN];
    int p = (*(volatile int*)&g_epoch) & 1;
    int t = threadIdx.x;
    if (t < NBIN) hcnt[t] = 0;
    __syncthreads();
    int base = blockIdx.x * 1024;
    int occ[4], pos[4];
#pragma unroll
    for (int j = 0; j < 4; j++) {
        int i = base + j * 256 + t;
        if (i < n) { occ[j] = xp[i] * KOCC + xo[i]; pos[j] = atomicAdd(&hcnt[occ[j]], 1); }
        else occ[j] = -1;
    }
    __syncthreads();
    if (t < NBIN && hcnt[t] > 0) hbase[t] = atomicAdd(&g_cursor2[p][t], hcnt[t]);
    __syncthreads();
#pragma unroll
    for (int j = 0; j < 4; j++)
        if (occ[j] >= 0) {
            int q = hbase[occ[j]] + pos[j];
            if (q < CAP) g_sorted[occ[j] * CAP + q] = base + j * 256 + t;
        }
}

// ---------------------------------------------------------------------------
// fp32 pair -> bf16x2 (hi) + bf16x2 (lo residual).  Lower 16 bits = first elem.
__device__ __forceinline__ void split2(float a, float b, uint32_t& hi, uint32_t& lo) {
    asm("cvt.rn.bf16x2.f32 %0, %1, %2;" : "=r"(hi) : "f"(b), "f"(a));
    float ha = __uint_as_float(hi << 16);
    float hb = __uint_as_float(hi & 0xffff0000u);
    float ra = a - ha, rb = b - hb;
    asm("cvt.rn.bf16x2.f32 %0, %1, %2;" : "=r"(lo) : "f"(rb), "f"(ra));
}

__device__ __forceinline__ void mma16816(float& d0, float& d1, float& d2, float& d3,
                                         uint32_t a0, uint32_t a1, uint32_t a2, uint32_t a3,
                                         uint32_t b0, uint32_t b1) {
    asm volatile(
        "mma.sync.aligned.m16n8k16.row.col.f32.bf16.bf16.f32 "
        "{%0,%1,%2,%3}, {%4,%5,%6,%7}, {%8,%9}, {%0,%1,%2,%3};"
        : "+f"(d0), "+f"(d1), "+f"(d2), "+f"(d3)
        : "r"(a0), "r"(a1), "r"(a2), "r"(a3), "r"(b0), "r"(b1));
}

__device__ __forceinline__ void cta_done() {
    int v = atomicAdd(&g_done, 1);
    if ((v & (NCTA_MAIN - 1)) == NCTA_MAIN - 1) atomicAdd(&g_epoch, 1);
}

// ---------------------------------------------------------------------------
// Permuted-k mapping (A and B identical, D unchanged):
//   slot "kpair tig"   <- actual kpair 2*tig  (within each k16 chunk)
//   slot "kpair tig+4" <- actual kpair 2*tig+1
// Mainloop is PASS-MAJOR: the 3 hi/lo passes each run 5 independent n-tiles,
// so dependent HMMAs on the same accumulators sit at distance 5 (asm volatile
// enforces program order; nt-major order serialized on HMMA latency).
__global__ __launch_bounds__(256, 3) void k_main(
    const float* __restrict__ X,
    const float* __restrict__ Wp, const float* __restrict__ bp,
    const float* __restrict__ Wo, const float* __restrict__ bo,
    const float* __restrict__ Ws, const float* __restrict__ bs2,
    const int* __restrict__ subj, float* __restrict__ out, int n)
{
    __shared__ int   rowidx[MT];
    __shared__ float biasz[NCOL];
    extern __shared__ uint32_t sm[];

    int p = (*(volatile int*)&g_epoch) & 1;
    int bin  = blockIdx.x;
    int t = threadIdx.x;

    if (bin == 0 && blockIdx.y == 0 && t < NBIN) g_cursor2[1 - p][t] = 0;

    int cnt  = g_cursor2[p][bin];
    int base = blockIdx.y * MT;
    if (base >= cnt) { if (t == 0) cta_done(); return; }
    int nrows = min(MT, cnt - base);
    int phase = bin >> 3, occl = bin & 7;
    int lane = t & 31, w = t >> 5;
    int g = lane >> 2, tig = lane & 3;

    if (t < MT)
        rowidx[t] = g_sorted[bin * CAP + base + ((t < nrows) ? t : 0)];
    if (t < NCOL)
        biasz[t] = (t < 16) ? bp[t]
                 : (t < 24) ? bo[phase * KOCC + (t - 16)]
                            : bs2[bin * KSUBJ + (t - 24)];

    auto wrow = [&](int col) -> const float* {
        if (col < 16)      return Wp + col * HDIM;
        else if (col < 24) return Wo + (phase * KOCC + col - 16) * HDIM;
        else               return Ws + (bin * KSUBJ + col - 24) * HDIM;
    };

    // ---- stage B panel (40 x 256) as bf16 hi/lo ---------------------------
#pragma unroll
    for (int j = 0; j < 10; j++) {
        int u   = t + j * 256;            // float4 index 0..2559
        int col = u >> 6, f = u & 63;     // f -> kpairs 2f, 2f+1
        float4 wv = ((const float4*)wrow(col))[f];
        uint32_t h0, l0, h1, l1;
        split2(wv.x, wv.y, h0, l0);
        split2(wv.z, wv.w, h1, l1);
        *(uint2*)&sm[B_HI + col * SBW + 2 * f] = make_uint2(h0, h1);
        *(uint2*)&sm[B_LO + col * SBW + 2 * f] = make_uint2(l0, l1);
    }
    __syncthreads();

    // ---- mainloop: A via LDG.128 (permuted-k), barrier-free ---------------
    const int r0 = w * 16;
    const float4* xr0 = (const float4*)(X + (size_t)rowidx[r0 + g] * HDIM);
    const float4* xr1 = (const float4*)(X + (size_t)rowidx[r0 + g + 8] * HDIM);

    float4 buf[3][2];                     // chunks c, c+1, c+2 in flight
#pragma unroll
    for (int c0 = 0; c0 < 2; c0++) {
        buf[c0][0] = xr0[c0 * 4 + tig];
        buf[c0][1] = xr1[c0 * 4 + tig];
    }

    float acc[5][4];
#pragma unroll
    for (int nt = 0; nt < 5; nt++)
#pragma unroll
        for (int i = 0; i < 4; i++) acc[nt][i] = 0.f;

#pragma unroll
    for (int c = 0; c < 16; c++) {        // chunk = k16 = one mma k-step
        float4* cur = buf[c % 3];
        if (c < 14) {
            float4* nx = buf[(c + 2) % 3];
            nx[0] = xr0[(c + 2) * 4 + tig];
            nx[1] = xr1[(c + 2) * 4 + tig];
        }
        // lane's float4 = actual kpairs 2tig (.x,.y) and 2tig+1 (.z,.w)
        uint32_t a0h, a0l, a1h, a1l, a2h, a2l, a3h, a3l;
        split2(cur[0].x, cur[0].y, a0h, a0l);   // slot "tig"   row g
        split2(cur[0].z, cur[0].w, a2h, a2l);   // slot "tig+4" row g
        split2(cur[1].x, cur[1].y, a1h, a1l);   // slot "tig"   row g+8
        split2(cur[1].z, cur[1].w, a3h, a3l);   // slot "tig+4" row g+8
        int kb = c * 8 + 2 * tig;               // actual kpair index for b0

        uint2 bh[5], bl[5];
#pragma unroll
        for (int nt = 0; nt < 5; nt++)
            bh[nt] = *(const uint2*)&sm[B_HI + (nt * 8 + g) * SBW + kb];
        // pass 1: hi * hi   (5 independent chains)
#pragma unroll
        for (int nt = 0; nt < 5; nt++)
            mma16816(acc[nt][0], acc[nt][1], acc[nt][2], acc[nt][3],
                     a0h, a1h, a2h, a3h, bh[nt].x, bh[nt].y);
        // bl loads issued here: 29cy LDS latency covered by pass 2
#pragma unroll
        for (int nt = 0; nt < 5; nt++)
            bl[nt] = *(const uint2*)&sm[B_LO + (nt * 8 + g) * SBW + kb];
        // pass 2: lo * hi   (reuses bh registers)
#pragma unroll
        for (int nt = 0; nt < 5; nt++)
            mma16816(acc[nt][0], acc[nt][1], acc[nt][2], acc[nt][3],
                     a0l, a1l, a2l, a3l, bh[nt].x, bh[nt].y);
        // pass 3: hi * lo
#pragma unroll
        for (int nt = 0; nt < 5; nt++)
            mma16816(acc[nt][0], acc[nt][1], acc[nt][2], acc[nt][3],
                     a0h, a1h, a2h, a3h, bl[nt].x, bl[nt].y);
    }

    // ---- epilogue: D -> smem logits [128][41] (aliases B), softmax --------
    __syncthreads();
    float* lg = (float*)sm;               // 5248 words <= 10880
#pragma unroll
    for (int nt = 0; nt < 5; nt++) {
        int col = nt * 8 + 2 * tig;
        lg[(r0 + g) * 41 + col]         = acc[nt][0];
        lg[(r0 + g) * 41 + col + 1]     = acc[nt][1];
        lg[(r0 + g + 8) * 41 + col]     = acc[nt][2];
        lg[(r0 + g + 8) * 41 + col + 1] = acc[nt][3];
    }
    __syncthreads();

    if (t < nrows) {
        const float* Lr = lg + t * 41;
        int orig = rowidx[t];
        float L[NCOL];
#pragma unroll
        for (int j = 0; j < NCOL; j++) L[j] = Lr[j] + biasz[j];

        float m1 = L[0];
#pragma unroll
        for (int j = 1; j < 16; j++) m1 = fmaxf(m1, L[j]);
        float s1 = 0.f;
#pragma unroll
        for (int j = 0; j < 16; j++) s1 += expf(L[j] - m1);
        float p1 = expf(L[phase] - m1) / s1;

        float m2 = L[16];
#pragma unroll
        for (int j = 17; j < 24; j++) m2 = fmaxf(m2, L[j]);
        float s2 = 0.f;
#pragma unroll
        for (int j = 16; j < 24; j++) s2 += expf(L[j] - m2);
        float p2 = expf(L[16 + occl] - m2) / s2;

        int sj = subj[orig];
        float m3 = L[24];
#pragma unroll
        for (int j = 25; j < 40; j++) m3 = fmaxf(m3, L[j]);
        float s3 = 0.f;
#pragma unroll
        for (int j = 24; j < 40; j++) s3 += expf(L[j] - m3);
        float p3 = expf(L[24 + sj] - m3) / s3;

        float po = p1 * p2;
        out[orig]         = p1;
        out[n + orig]     = po;
        out[2 * n + orig] = po * p3;
    }

    __syncthreads();
    if (t == 0) cta_done();
}

// ---------------------------------------------------------------------------
extern "C" void kernel_launch(void* const* d_in, const int* in_sizes, int n_in,
                              void* d_out, int out_size) {
    const float* X  = (const float*)d_in[0];
    const float* Wp = (const float*)d_in[1];
    const float* bp = (const float*)d_in[2];
    const float* Wo = (const float*)d_in[3];
    const float* bo = (const float*)d_in[4];
    const float* Ws = (const float*)d_in[5];
    const float* bs = (const float*)d_in[6];
    const int*   xp = (const int*)d_in[7];
    const int*   xo = (const int*)d_in[8];
    const int*   xs = (const int*)d_in[9];
    int n = in_sizes[0] / HDIM;
    float* out = (float*)d_out;

    static int cfg = 0;
    if (!cfg) {
        cudaFuncSetAttribute(k_main, cudaFuncAttributeMaxDynamicSharedMemorySize,
                             DSM_WORDS * 4);
        cfg = 1;
    }

    k_scatter<<<(n + 1023) / 1024, 256>>>(xp, xo, n);
    dim3 grid(NBIN, NYT);
    k_main<<<grid, 256, DSM_WORDS * 4>>>(X, Wp, bp, Wo, bo, Ws, bs, xs, out, n);
}